// round 1
// baseline (speedup 1.0000x reference)
#include <cuda_runtime.h>

#define BATCH 8
#define SEQ   1024
#define EMB   512
#define HEADS 8
#define DK    64
#define NW    8
#define BH    (BATCH*HEADS)

// Precomputed per-token, per-wire cos/sin tables, wire-major so that a
// j-pair (j, j+1) is an 8-byte contiguous load. [bh][w][s]
__device__ float g_cos[BH*NW*SEQ];
__device__ float g_sin[BH*NW*SEQ];

// ---- packed f32x2 helpers (FFMA2 path: only reachable via PTX) ----
static __device__ __forceinline__ unsigned long long f2_pack(float x, float y){
    unsigned long long r;
    asm("mov.b64 %0, {%1, %2};" : "=l"(r) : "f"(x), "f"(y));
    return r;
}
static __device__ __forceinline__ float2 f2_unpack(unsigned long long v){
    float2 r;
    asm("mov.b64 {%0, %1}, %2;" : "=f"(r.x), "=f"(r.y) : "l"(v));
    return r;
}
static __device__ __forceinline__ unsigned long long f2_fma(unsigned long long a,
                                                            unsigned long long b,
                                                            unsigned long long c){
    unsigned long long d;
    asm("fma.rn.f32x2 %0, %1, %2, %3;" : "=l"(d) : "l"(a), "l"(b), "l"(c));
    return d;
}
static __device__ __forceinline__ unsigned long long f2_mul(unsigned long long a,
                                                            unsigned long long b){
    unsigned long long d;
    asm("mul.rn.f32x2 %0, %1, %2;" : "=l"(d) : "l"(a), "l"(b));
    return d;
}
static __device__ __forceinline__ unsigned long long f2_add(unsigned long long a,
                                                            unsigned long long b){
    unsigned long long d;
    asm("add.rn.f32x2 %0, %1, %2;" : "=l"(d) : "l"(a), "l"(b));
    return d;
}

// Pass 1: cos/sin of x[..., :8]*0.5 per (b,h,s,w). 64K threads.
__global__ void precompute_cs(const float* __restrict__ x){
    int idx = blockIdx.x * blockDim.x + threadIdx.x;   // 0 .. BH*SEQ-1
    int bh = idx >> 10;
    int s  = idx & (SEQ-1);
    int b  = bh >> 3, h = bh & 7;
    const float* xp = x + ((size_t)(b*SEQ + s))*EMB + h*DK;
#pragma unroll
    for (int w = 0; w < NW; ++w){
        float sn, cs;
        sincosf(0.5f * xp[w], &sn, &cs);
        g_cos[(bh*NW + w)*SEQ + s] = cs;
        g_sin[(bh*NW + w)*SEQ + s] = sn;
    }
}

// Pass 2: fused score + softmax + PV. One thread = one output row i.
// Grid: (SEQ/128, BH), 128 threads/CTA.
__global__ void __launch_bounds__(128, 1)
qk_attn(const float* __restrict__ x, float* __restrict__ out){
    __shared__ __align__(16) float sC[NW][128];
    __shared__ __align__(16) float sS[NW][128];
    __shared__ __align__(16) float sV[128*DK];

    const int bh  = blockIdx.y;
    const int b   = bh >> 3, h = bh & 7;
    const int tid = threadIdx.x;
    const int i   = blockIdx.x*128 + tid;

    // Per-row wire cos/sin broadcast into both f32x2 lanes.
    unsigned long long ciP[NW], siP[NW];
#pragma unroll
    for (int w = 0; w < NW; ++w){
        float c = g_cos[(bh*NW + w)*SEQ + i];
        float s = g_sin[(bh*NW + w)*SEQ + i];
        ciP[w] = f2_pack(c, c);
        siP[w] = f2_pack(s, s);
    }

    unsigned long long acc[DK/2];
#pragma unroll
    for (int d = 0; d < DK/2; ++d) acc[d] = 0ULL;
    unsigned long long psum = 0ULL;

    const float4* x4 = (const float4*)x;

    for (int jt = 0; jt < SEQ/128; ++jt){
        const int j0 = jt*128;

        // --- cooperative tile load ---
        {   // cos/sin planes: 8 wires x 128 j = 1024 floats each
            int w  = tid >> 4;           // 0..7
            int jj = (tid & 15) * 8;     // 0,8,...,120
            const float4* gc = (const float4*)(g_cos + (bh*NW + w)*SEQ + j0 + jj);
            const float4* gs = (const float4*)(g_sin + (bh*NW + w)*SEQ + j0 + jj);
            *(float4*)&sC[w][jj]     = gc[0];
            *(float4*)&sC[w][jj + 4] = gc[1];
            *(float4*)&sS[w][jj]     = gs[0];
            *(float4*)&sS[w][jj + 4] = gs[1];
        }
        {   // V tile: 128 rows x 64 floats = 2048 float4
#pragma unroll
            for (int r = 0; r < 16; ++r){
                int l   = tid + r*128;
                int row = l >> 4;
                int d4  = l & 15;
                ((float4*)sV)[row*16 + d4] =
                    x4[(size_t)(b*SEQ + j0 + row)*(EMB/4) + h*(DK/4) + d4];
            }
        }
        __syncthreads();

        // --- 64 j-pairs, everything 2-wide in f32x2 ---
        for (int jp = 0; jp < 64; ++jp){
            unsigned long long prod;
            {
                unsigned long long c0 = ((const unsigned long long*)sC[0])[jp];
                unsigned long long s0 = ((const unsigned long long*)sS[0])[jp];
                prod = f2_fma(siP[0], s0, f2_mul(ciP[0], c0));
            }
#pragma unroll
            for (int w = 1; w < NW; ++w){
                unsigned long long c = ((const unsigned long long*)sC[w])[jp];
                unsigned long long s = ((const unsigned long long*)sS[w])[jp];
                unsigned long long t = f2_fma(siP[w], s, f2_mul(ciP[w], c));
                prod = f2_mul(prod, t);
            }
            float2 pr = f2_unpack(prod);
            // softmax max is exactly 1 (diagonal), scores in [0,1] -> raw exp is safe
            float p0 = __expf(fabsf(pr.x));
            float p1 = __expf(fabsf(pr.y));
            psum = f2_add(psum, f2_pack(p0, p1));

            unsigned long long p0P = f2_pack(p0, p0);
            unsigned long long p1P = f2_pack(p1, p1);
            const unsigned long long* v0 =
                (const unsigned long long*)(sV + (2*jp)*DK);
            const unsigned long long* v1 =
                (const unsigned long long*)(sV + (2*jp + 1)*DK);
#pragma unroll
            for (int d = 0; d < DK/2; ++d)
                acc[d] = f2_fma(p0P, v0[d], acc[d]);
#pragma unroll
            for (int d = 0; d < DK/2; ++d)
                acc[d] = f2_fma(p1P, v1[d], acc[d]);
        }
        __syncthreads();
    }

    float2 sm = f2_unpack(psum);
    float inv = 1.0f / (sm.x + sm.y);
    float* op = out + ((size_t)(b*SEQ + i))*EMB + h*DK;
#pragma unroll
    for (int d = 0; d < DK/2; d += 2){
        float2 a  = f2_unpack(acc[d]);
        float2 b2 = f2_unpack(acc[d + 1]);
        ((float4*)op)[d >> 1] = make_float4(a.x*inv, a.y*inv, b2.x*inv, b2.y*inv);
    }
}

extern "C" void kernel_launch(void* const* d_in, const int* in_sizes, int n_in,
                              void* d_out, int out_size){
    const float* x = (const float*)d_in[0];
    float* out = (float*)d_out;
    precompute_cs<<<(BH*SEQ)/256, 256>>>(x);
    dim3 grid(SEQ/128, BH);
    qk_attn<<<grid, 128>>>(x, out);
}

// round 4
// speedup vs baseline: 1.0944x; 1.0944x over previous
#include <cuda_runtime.h>

#define BATCH 8
#define SEQ   1024
#define EMB   512
#define HEADS 8
#define DK    64
#define NW    8
#define BH    (BATCH*HEADS)
#define TM    128          // rows per CTA
#define TJ    64           // j-tile
#define VSTR  72           // V smem row stride (floats): bank=(8*tig+g+8*nb)%32 -> conflict-free

typedef unsigned long long u64;

// Precomputed tables (device globals; allocation is forbidden)
__device__ float2 g_cc[BH*NW*SEQ];          // (cos, cos) duplicated for f32x2 broadcast
__device__ float2 g_ss[BH*NW*SEQ];          // (sin, sin)
__device__ float  g_vh[(size_t)BH*SEQ*DK];  // V rounded to tf32 (hi part, fp32 bits)
__device__ float  g_vl[(size_t)BH*SEQ*DK];  // tf32(V - Vhi) (lo part)

// ---- packed f32x2 helpers ----
static __device__ __forceinline__ u64 f2_pack(float x, float y){
    u64 r; asm("mov.b64 %0, {%1, %2};" : "=l"(r) : "f"(x), "f"(y)); return r;
}
static __device__ __forceinline__ float2 f2_unpack(u64 v){
    float2 r; asm("mov.b64 {%0, %1}, %2;" : "=f"(r.x), "=f"(r.y) : "l"(v)); return r;
}
static __device__ __forceinline__ u64 f2_fma(u64 a, u64 b, u64 c){
    u64 d; asm("fma.rn.f32x2 %0, %1, %2, %3;" : "=l"(d) : "l"(a), "l"(b), "l"(c)); return d;
}
static __device__ __forceinline__ u64 f2_mul(u64 a, u64 b){
    u64 d; asm("mul.rn.f32x2 %0, %1, %2;" : "=l"(d) : "l"(a), "l"(b)); return d;
}
static __device__ __forceinline__ u64 f2_add(u64 a, u64 b){
    u64 d; asm("add.rn.f32x2 %0, %1, %2;" : "=l"(d) : "l"(a), "l"(b)); return d;
}
static __device__ __forceinline__ unsigned cvt_tf32(float f){
    unsigned r; asm("cvt.rna.tf32.f32 %0, %1;" : "=r"(r) : "f"(f)); return r;
}

// Pass 1: per-token tables.
__global__ void precompute(const float* __restrict__ x){
    int idx = blockIdx.x*blockDim.x + threadIdx.x;   // bh*SEQ + s
    int bh = idx >> 10, s = idx & (SEQ-1);
    int b = bh >> 3, h = bh & 7;
    const float* xp = x + ((size_t)(b*SEQ + s))*EMB + h*DK;
#pragma unroll
    for (int w = 0; w < NW; ++w){
        float sn, cs;
        sincosf(0.5f*xp[w], &sn, &cs);
        g_cc[(bh*NW + w)*SEQ + s] = make_float2(cs, cs);
        g_ss[(bh*NW + w)*SEQ + s] = make_float2(sn, sn);
    }
    float* vh = g_vh + (size_t)idx*DK;
    float* vl = g_vl + (size_t)idx*DK;
#pragma unroll
    for (int d = 0; d < DK; ++d){
        float v  = xp[d];
        float hi = __uint_as_float(cvt_tf32(v));
        vh[d] = hi;
        vl[d] = __uint_as_float(cvt_tf32(v - hi));
    }
}

// Pass 2: fused score -> exp -> tensor-core PV (fp32-split tf32) -> normalize.
// 8 warps; warp w owns rows [w*16, w*16+16). Thread (g,tig) computes P for
// rows {g, g+8} at j = 8*kb + {tig, tig+4}: the m16n8k8 tf32 A fragment.
__global__ void __launch_bounds__(256, 2)
qk_attn2(float* __restrict__ out){
    __shared__ __align__(16) float2 sCC[NW][TJ];
    __shared__ __align__(16) float2 sSS[NW][TJ];
    __shared__ __align__(16) float  sVh[TJ*VSTR];
    __shared__ __align__(16) float  sVl[TJ*VSTR];

    const int bh = blockIdx.y, b = bh >> 3, h = bh & 7;
    const int tid = threadIdx.x;
    const int w   = tid >> 5;
    const int lane = tid & 31;
    const int g   = lane >> 2, tig = lane & 3;
    const int i0  = blockIdx.x*TM + w*16 + g;
    const int i1  = i0 + 8;

    u64 ciP[NW], siP[NW];
#pragma unroll
    for (int q = 0; q < NW; ++q){
        const float2* cc = &g_cc[(bh*NW + q)*SEQ];
        const float2* ss = &g_ss[(bh*NW + q)*SEQ];
        ciP[q] = f2_pack(cc[i0].x, cc[i1].x);
        siP[q] = f2_pack(ss[i0].x, ss[i1].x);
    }

    float acc[8][4];
#pragma unroll
    for (int nb = 0; nb < 8; ++nb)
#pragma unroll
        for (int k = 0; k < 4; ++k) acc[nb][k] = 0.f;
    u64 psum = 0ULL;

    for (int jt = 0; jt < SEQ/TJ; ++jt){
        const int j0 = jt*TJ;
#pragma unroll
        for (int r = 0; r < 2; ++r){
            int e = tid + r*256;
            int wi = e >> 6, jj = e & 63;
            sCC[wi][jj] = g_cc[(bh*NW + wi)*SEQ + j0 + jj];
            sSS[wi][jj] = g_ss[(bh*NW + wi)*SEQ + j0 + jj];
        }
#pragma unroll
        for (int r = 0; r < 4; ++r){
            int l = tid + r*256;
            int row = l >> 4, c4 = l & 15;
            size_t gidx = ((size_t)bh*SEQ + j0 + row)*(DK/4) + c4;
            *(float4*)&sVh[row*VSTR + c4*4] = ((const float4*)g_vh)[gidx];
            *(float4*)&sVl[row*VSTR + c4*4] = ((const float4*)g_vl)[gidx];
        }
        __syncthreads();

#pragma unroll
        for (int kb = 0; kb < 8; ++kb){
            const int ja = kb*8 + tig, jb = ja + 4;
            u64 prodA = f2_fma(siP[0], *(const u64*)&sSS[0][ja],
                               f2_mul(ciP[0], *(const u64*)&sCC[0][ja]));
            u64 prodB = f2_fma(siP[0], *(const u64*)&sSS[0][jb],
                               f2_mul(ciP[0], *(const u64*)&sCC[0][jb]));
#pragma unroll
            for (int q = 1; q < NW; ++q){
                u64 tA = f2_fma(siP[q], *(const u64*)&sSS[q][ja],
                                f2_mul(ciP[q], *(const u64*)&sCC[q][ja]));
                u64 tB = f2_fma(siP[q], *(const u64*)&sSS[q][jb],
                                f2_mul(ciP[q], *(const u64*)&sCC[q][jb]));
                prodA = f2_mul(prodA, tA);
                prodB = f2_mul(prodB, tB);
            }
            float2 pA = f2_unpack(prodA), pB = f2_unpack(prodB);
            // diagonal score = 1 is the softmax max -> raw exp is safe
            float e0 = __expf(fabsf(pA.x));   // p(i0, ja)
            float e1 = __expf(fabsf(pA.y));   // p(i1, ja)
            float e2 = __expf(fabsf(pB.x));   // p(i0, jb)
            float e3 = __expf(fabsf(pB.y));   // p(i1, jb)
            // lane x accumulates row i0 (e0+e2), lane y row i1 (e1+e3)
            psum = f2_add(psum, f2_add(f2_pack(e0, e1), f2_pack(e2, e3)));

            // fp32-split A fragments: hi = tf32(e), lo = tf32(e - hi)
            unsigned ah0 = cvt_tf32(e0), ah1 = cvt_tf32(e1);
            unsigned ah2 = cvt_tf32(e2), ah3 = cvt_tf32(e3);
            unsigned al0 = cvt_tf32(e0 - __uint_as_float(ah0));
            unsigned al1 = cvt_tf32(e1 - __uint_as_float(ah1));
            unsigned al2 = cvt_tf32(e2 - __uint_as_float(ah2));
            unsigned al3 = cvt_tf32(e3 - __uint_as_float(ah3));

            const float* vAh = &sVh[ja*VSTR + g];
            const float* vBh = &sVh[jb*VSTR + g];
            const float* vAl = &sVl[ja*VSTR + g];
            const float* vBl = &sVl[jb*VSTR + g];
#pragma unroll
            for (int nb = 0; nb < 8; ++nb){
                unsigned bh0 = __float_as_uint(vAh[nb*8]);
                unsigned bh1 = __float_as_uint(vBh[nb*8]);
                unsigned bl0 = __float_as_uint(vAl[nb*8]);
                unsigned bl1 = __float_as_uint(vBl[nb*8]);
                asm volatile(
                    "mma.sync.aligned.m16n8k8.row.col.f32.tf32.tf32.f32 "
                    "{%0,%1,%2,%3}, {%4,%5,%6,%7}, {%8,%9}, {%0,%1,%2,%3};"
                    : "+f"(acc[nb][0]), "+f"(acc[nb][1]),
                      "+f"(acc[nb][2]), "+f"(acc[nb][3])
                    : "r"(al0), "r"(al1), "r"(al2), "r"(al3), "r"(bh0), "r"(bh1));
                asm volatile(
                    "mma.sync.aligned.m16n8k8.row.col.f32.tf32.tf32.f32 "
                    "{%0,%1,%2,%3}, {%4,%5,%6,%7}, {%8,%9}, {%0,%1,%2,%3};"
                    : "+f"(acc[nb][0]), "+f"(acc[nb][1]),
                      "+f"(acc[nb][2]), "+f"(acc[nb][3])
                    : "r"(ah0), "r"(ah1), "r"(ah2), "r"(ah3), "r"(bl0), "r"(bl1));
                asm volatile(
                    "mma.sync.aligned.m16n8k8.row.col.f32.tf32.tf32.f32 "
                    "{%0,%1,%2,%3}, {%4,%5,%6,%7}, {%8,%9}, {%0,%1,%2,%3};"
                    : "+f"(acc[nb][0]), "+f"(acc[nb][1]),
                      "+f"(acc[nb][2]), "+f"(acc[nb][3])
                    : "r"(ah0), "r"(ah1), "r"(ah2), "r"(ah3), "r"(bh0), "r"(bh1));
            }
        }
        __syncthreads();
    }

    // psum lanes = (row i0, row i1); reduce over the 4 tig lanes
    float2 ps = f2_unpack(psum);
    ps.x += __shfl_xor_sync(0xffffffffu, ps.x, 1);
    ps.x += __shfl_xor_sync(0xffffffffu, ps.x, 2);
    ps.y += __shfl_xor_sync(0xffffffffu, ps.y, 1);
    ps.y += __shfl_xor_sync(0xffffffffu, ps.y, 2);
    const float inv0 = 1.0f/ps.x, inv1 = 1.0f/ps.y;

#pragma unroll
    for (int nb = 0; nb < 8; ++nb){
        size_t o0 = ((size_t)(b*SEQ + i0))*EMB + h*DK + nb*8 + 2*tig;
        size_t o1 = ((size_t)(b*SEQ + i1))*EMB + h*DK + nb*8 + 2*tig;
        *(float2*)&out[o0] = make_float2(acc[nb][0]*inv0, acc[nb][1]*inv0);
        *(float2*)&out[o1] = make_float2(acc[nb][2]*inv1, acc[nb][3]*inv1);
    }
}

extern "C" void kernel_launch(void* const* d_in, const int* in_sizes, int n_in,
                              void* d_out, int out_size){
    const float* x = (const float*)d_in[0];
    float* out = (float*)d_out;
    precompute<<<(BH*SEQ)/256, 256>>>(x);
    dim3 grid(SEQ/TM, BH);
    qk_attn2<<<grid, 256>>>(out);
}

// round 6
// speedup vs baseline: 1.7701x; 1.6175x over previous
#include <cuda_runtime.h>

#define BATCH 8
#define SEQ   1024
#define EMB   512
#define HEADS 8
#define DK    64
#define NW    8
#define BH    (BATCH*HEADS)
#define TM    128          // rows per CTA
#define TJ    64           // j-tile
#define VSTR  72           // V smem row stride (floats): bank=(8*tig+g+8*nb)%32 -> conflict-free

// Precomputed tables (device globals; allocation is forbidden)
__device__ float2 g_cs[BH*NW*SEQ];          // (cos, sin) per (bh, wire, s)
__device__ float  g_vh[(size_t)BH*SEQ*DK];  // V rounded to tf32 (fp32 bit layout)

static __device__ __forceinline__ unsigned cvt_tf32(float f){
    unsigned r; asm("cvt.rna.tf32.f32 %0, %1;" : "=r"(r) : "f"(f)); return r;
}

// Pass 1a: cos/sin table. One thread per (bh, w, s): 512K threads.
__global__ void precompute_cs(const float* __restrict__ x){
    int idx = blockIdx.x*blockDim.x + threadIdx.x;      // (bh*NW + w)*SEQ + s
    int s   = idx & (SEQ-1);
    int bhw = idx >> 10;
    int w   = bhw & (NW-1);
    int bh  = bhw >> 3;
    int b = bh >> 3, h = bh & 7;
    float v = x[((size_t)(b*SEQ + s))*EMB + h*DK + w];
    float sn, cs;
    sincosf(0.5f*v, &sn, &cs);
    g_cs[idx] = make_float2(cs, sn);
}

// Pass 1b: tf32-rounded V. One thread per float4: 1M threads.
__global__ void precompute_vh(const float* __restrict__ x){
    int idx = blockIdx.x*blockDim.x + threadIdx.x;      // (bh*SEQ+s)*16 + d4
    int d4  = idx & 15;
    int bhs = idx >> 4;
    int s   = bhs & (SEQ-1);
    int bh  = bhs >> 10;
    int b = bh >> 3, h = bh & 7;
    float4 v = ((const float4*)x)[((size_t)(b*SEQ + s))*(EMB/4) + h*(DK/4) + d4];
    float4 o;
    o.x = __uint_as_float(cvt_tf32(v.x));
    o.y = __uint_as_float(cvt_tf32(v.y));
    o.z = __uint_as_float(cvt_tf32(v.z));
    o.w = __uint_as_float(cvt_tf32(v.w));
    ((float4*)g_vh)[idx] = o;
}

// Pass 2: fused score -> exp -> tensor-core PV (P fp32-split, V tf32) -> normalize.
// 8 warps; warp w owns rows [w*16, w*16+16). Thread (g,tig) computes P for
// rows {g, g+8} at j = 8*kb + {tig, tig+4}: the m16n8k8 tf32 A fragment.
__global__ void __launch_bounds__(256, 2)
qk_attn3(float* __restrict__ out){
    __shared__ __align__(16) float2 sCS[NW][TJ];   // (cos, sin)
    __shared__ __align__(16) float  sVh[TJ*VSTR];

    const int bh = blockIdx.y, b = bh >> 3, h = bh & 7;
    const int tid = threadIdx.x;
    const int w   = tid >> 5;
    const int lane = tid & 31;
    const int g   = lane >> 2, tig = lane & 3;
    const int i0  = blockIdx.x*TM + w*16 + g;
    const int i1  = i0 + 8;

    // i-side wire values, scalar per row
    float ci0[NW], si0[NW], ci1[NW], si1[NW];
#pragma unroll
    for (int q = 0; q < NW; ++q){
        float2 a = g_cs[(bh*NW + q)*SEQ + i0];
        float2 c = g_cs[(bh*NW + q)*SEQ + i1];
        ci0[q] = a.x; si0[q] = a.y;
        ci1[q] = c.x; si1[q] = c.y;
    }

    float acc[8][4];
#pragma unroll
    for (int nb = 0; nb < 8; ++nb)
#pragma unroll
        for (int k = 0; k < 4; ++k) acc[nb][k] = 0.f;
    float ps0 = 0.f, ps1 = 0.f;

    for (int jt = 0; jt < SEQ/TJ; ++jt){
        const int j0 = jt*TJ;
        // stage (c,s) tile: 8 wires x 64 j float2 = 512 entries, 2 per thread
#pragma unroll
        for (int r = 0; r < 2; ++r){
            int e = tid + r*256;
            int wi = e >> 6, jj = e & 63;
            sCS[wi][jj] = g_cs[(bh*NW + wi)*SEQ + j0 + jj];
        }
        // stage V tile: 64 rows x 16 float4 = 1024 float4 -> 4 per thread
#pragma unroll
        for (int r = 0; r < 4; ++r){
            int l = tid + r*256;
            int row = l >> 4, c4 = l & 15;
            *(float4*)&sVh[row*VSTR + c4*4] =
                ((const float4*)g_vh)[((size_t)bh*SEQ + j0 + row)*(DK/4) + c4];
        }
        __syncthreads();

#pragma unroll
        for (int kb = 0; kb < 8; ++kb){
            const int ja = kb*8 + tig, jb = ja + 4;
            // scalar score products for (rows i0,i1) x (cols ja,jb)
            float2 t = sCS[0][ja];
            float pA0 = ci0[0]*t.x + si0[0]*t.y;
            float pA1 = ci1[0]*t.x + si1[0]*t.y;
            float2 u = sCS[0][jb];
            float pB0 = ci0[0]*u.x + si0[0]*u.y;
            float pB1 = ci1[0]*u.x + si1[0]*u.y;
#pragma unroll
            for (int q = 1; q < NW; ++q){
                t = sCS[q][ja];
                pA0 *= ci0[q]*t.x + si0[q]*t.y;
                pA1 *= ci1[q]*t.x + si1[q]*t.y;
                u = sCS[q][jb];
                pB0 *= ci0[q]*u.x + si0[q]*u.y;
                pB1 *= ci1[q]*u.x + si1[q]*u.y;
            }
            // diagonal score = 1 is the softmax max -> raw exp is safe
            float e0 = __expf(fabsf(pA0));   // p(i0, ja)
            float e1 = __expf(fabsf(pA1));   // p(i1, ja)
            float e2 = __expf(fabsf(pB0));   // p(i0, jb)
            float e3 = __expf(fabsf(pB1));   // p(i1, jb)
            ps0 += e0 + e2;
            ps1 += e1 + e3;

            // P fp32-split: hi = tf32(e), lo = tf32(e - hi); V is tf32 (hi only)
            unsigned ah0 = cvt_tf32(e0), ah1 = cvt_tf32(e1);
            unsigned ah2 = cvt_tf32(e2), ah3 = cvt_tf32(e3);
            unsigned al0 = cvt_tf32(e0 - __uint_as_float(ah0));
            unsigned al1 = cvt_tf32(e1 - __uint_as_float(ah1));
            unsigned al2 = cvt_tf32(e2 - __uint_as_float(ah2));
            unsigned al3 = cvt_tf32(e3 - __uint_as_float(ah3));

            const float* vA = &sVh[ja*VSTR + g];
            const float* vB = &sVh[jb*VSTR + g];
#pragma unroll
            for (int nb = 0; nb < 8; ++nb){
                unsigned b0 = __float_as_uint(vA[nb*8]);
                unsigned b1 = __float_as_uint(vB[nb*8]);
                asm volatile(
                    "mma.sync.aligned.m16n8k8.row.col.f32.tf32.tf32.f32 "
                    "{%0,%1,%2,%3}, {%4,%5,%6,%7}, {%8,%9}, {%0,%1,%2,%3};"
                    : "+f"(acc[nb][0]), "+f"(acc[nb][1]),
                      "+f"(acc[nb][2]), "+f"(acc[nb][3])
                    : "r"(al0), "r"(al1), "r"(al2), "r"(al3), "r"(b0), "r"(b1));
                asm volatile(
                    "mma.sync.aligned.m16n8k8.row.col.f32.tf32.tf32.f32 "
                    "{%0,%1,%2,%3}, {%4,%5,%6,%7}, {%8,%9}, {%0,%1,%2,%3};"
                    : "+f"(acc[nb][0]), "+f"(acc[nb][1]),
                      "+f"(acc[nb][2]), "+f"(acc[nb][3])
                    : "r"(ah0), "r"(ah1), "r"(ah2), "r"(ah3), "r"(b0), "r"(b1));
            }
        }
        __syncthreads();
    }

    // row sums: reduce over the 4 tig lanes (xor 1, 2)
    ps0 += __shfl_xor_sync(0xffffffffu, ps0, 1);
    ps0 += __shfl_xor_sync(0xffffffffu, ps0, 2);
    ps1 += __shfl_xor_sync(0xffffffffu, ps1, 1);
    ps1 += __shfl_xor_sync(0xffffffffu, ps1, 2);
    const float inv0 = 1.0f/ps0, inv1 = 1.0f/ps1;

#pragma unroll
    for (int nb = 0; nb < 8; ++nb){
        size_t o0 = ((size_t)(b*SEQ + i0))*EMB + h*DK + nb*8 + 2*tig;
        size_t o1 = ((size_t)(b*SEQ + i1))*EMB + h*DK + nb*8 + 2*tig;
        *(float2*)&out[o0] = make_float2(acc[nb][0]*inv0, acc[nb][1]*inv0);
        *(float2*)&out[o1] = make_float2(acc[nb][2]*inv1, acc[nb][3]*inv1);
    }
}

extern "C" void kernel_launch(void* const* d_in, const int* in_sizes, int n_in,
                              void* d_out, int out_size){
    const float* x = (const float*)d_in[0];
    float* out = (float*)d_out;
    precompute_cs<<<(BH*NW*SEQ)/256, 256>>>(x);
    precompute_vh<<<((size_t)BH*SEQ*16)/256, 256>>>(x);
    dim3 grid(SEQ/TM, BH);
    qk_attn3<<<grid, 256>>>(out);
}

// round 7
// speedup vs baseline: 1.8205x; 1.0285x over previous
#include <cuda_runtime.h>

#define BATCH 8
#define SEQ   1024
#define EMB   512
#define HEADS 8
#define DK    64
#define NW    8
#define BH    (BATCH*HEADS)
#define TM    128          // rows per CTA (4 warps x m=32)
#define TJ    64           // j-tile
#define VSTR  72           // V smem row stride (floats): bank=(8*tig+g+8*nb)%32 -> conflict-free

// Precomputed tables (device globals; allocation is forbidden)
__device__ float2 g_cs[BH*NW*SEQ];          // (cos, sin) per (bh, wire, s)
__device__ float  g_vh[(size_t)BH*SEQ*DK];  // V rounded to tf32 (fp32 bit layout)

static __device__ __forceinline__ unsigned cvt_tf32(float f){
    unsigned r; asm("cvt.rna.tf32.f32 %0, %1;" : "=r"(r) : "f"(f)); return r;
}

// Pass 1a: cos/sin table. One thread per (bh, w, s): 512K threads.
__global__ void precompute_cs(const float* __restrict__ x){
    int idx = blockIdx.x*blockDim.x + threadIdx.x;      // (bh*NW + w)*SEQ + s
    int s   = idx & (SEQ-1);
    int bhw = idx >> 10;
    int w   = bhw & (NW-1);
    int bh  = bhw >> 3;
    int b = bh >> 3, h = bh & 7;
    float v = x[((size_t)(b*SEQ + s))*EMB + h*DK + w];
    float sn, cs;
    sincosf(0.5f*v, &sn, &cs);
    g_cs[idx] = make_float2(cs, sn);
}

// Pass 1b: tf32-rounded V. One thread per float4: 1M threads.
__global__ void precompute_vh(const float* __restrict__ x){
    int idx = blockIdx.x*blockDim.x + threadIdx.x;      // (bh*SEQ+s)*16 + d4
    int d4  = idx & 15;
    int bhs = idx >> 4;
    int s   = bhs & (SEQ-1);
    int bh  = bhs >> 10;
    int b = bh >> 3, h = bh & 7;
    float4 v = ((const float4*)x)[((size_t)(b*SEQ + s))*(EMB/4) + h*(DK/4) + d4];
    float4 o;
    o.x = __uint_as_float(cvt_tf32(v.x));
    o.y = __uint_as_float(cvt_tf32(v.y));
    o.z = __uint_as_float(cvt_tf32(v.z));
    o.w = __uint_as_float(cvt_tf32(v.w));
    ((float4*)g_vh)[idx] = o;
}

// Pass 2: fused score -> exp -> tensor-core PV -> normalize.
// 4 warps; warp w owns rows [w*32, w*32+32) as TWO m16 MMA blocks that SHARE
// B fragments. Thread (g,tig): rows {g, g+8, g+16, g+24}, cols j=8kb+{tig,tig+4}.
__global__ void __launch_bounds__(128, 2)
qk_attn4(float* __restrict__ out){
    __shared__ __align__(16) float2 sCS[NW][TJ];   // (cos, sin)
    __shared__ __align__(16) float  sVh[TJ*VSTR];

    const int bh = blockIdx.y, b = bh >> 3, h = bh & 7;
    const int tid = threadIdx.x;
    const int w   = tid >> 5;
    const int lane = tid & 31;
    const int g   = lane >> 2, tig = lane & 3;
    const int ibase = blockIdx.x*TM + w*32 + g;   // row r -> ibase + 8r

    // i-side wire values for the thread's 4 rows
    float ci[4][NW], si[4][NW];
#pragma unroll
    for (int r = 0; r < 4; ++r)
#pragma unroll
        for (int q = 0; q < NW; ++q){
            float2 a = g_cs[(bh*NW + q)*SEQ + ibase + 8*r];
            ci[r][q] = a.x; si[r][q] = a.y;
        }

    float acc0[8][4], acc1[8][4];   // block0: rows g,g+8; block1: rows g+16,g+24
#pragma unroll
    for (int nb = 0; nb < 8; ++nb)
#pragma unroll
        for (int k = 0; k < 4; ++k){ acc0[nb][k] = 0.f; acc1[nb][k] = 0.f; }
    float ps[4] = {0.f, 0.f, 0.f, 0.f};

    for (int jt = 0; jt < SEQ/TJ; ++jt){
        const int j0 = jt*TJ;
        // stage (c,s) tile: 512 float2 -> 4 per thread
#pragma unroll
        for (int r = 0; r < 4; ++r){
            int e = tid + r*128;
            int wi = e >> 6, jj = e & 63;
            sCS[wi][jj] = g_cs[(bh*NW + wi)*SEQ + j0 + jj];
        }
        // stage V tile: 64 rows x 16 float4 = 1024 float4 -> 8 per thread
#pragma unroll
        for (int r = 0; r < 8; ++r){
            int l = tid + r*128;
            int row = l >> 4, c4 = l & 15;
            *(float4*)&sVh[row*VSTR + c4*4] =
                ((const float4*)g_vh)[((size_t)bh*SEQ + j0 + row)*(DK/4) + c4];
        }
        __syncthreads();

#pragma unroll
        for (int kb = 0; kb < 8; ++kb){
            const int ja = kb*8 + tig, jb = ja + 4;
            // 8 score products: 4 rows x 2 cols
            float pA[4], pB[4];
            {
                float2 t = sCS[0][ja], u = sCS[0][jb];
#pragma unroll
                for (int r = 0; r < 4; ++r){
                    pA[r] = ci[r][0]*t.x + si[r][0]*t.y;
                    pB[r] = ci[r][0]*u.x + si[r][0]*u.y;
                }
            }
#pragma unroll
            for (int q = 1; q < NW; ++q){
                float2 t = sCS[q][ja], u = sCS[q][jb];
#pragma unroll
                for (int r = 0; r < 4; ++r){
                    pA[r] *= ci[r][q]*t.x + si[r][q]*t.y;
                    pB[r] *= ci[r][q]*u.x + si[r][q]*u.y;
                }
            }
            // diagonal score = 1 is the softmax max -> raw exp is safe
            float eA[4], eB[4];
#pragma unroll
            for (int r = 0; r < 4; ++r){
                eA[r] = __expf(fabsf(pA[r]));
                eB[r] = __expf(fabsf(pB[r]));
                ps[r] += eA[r] + eB[r];
            }
            // P fp32-split A-fragments for the two m16 blocks
            unsigned ah[8], al[8];   // [block*4 + frag]
#pragma unroll
            for (int blk = 0; blk < 2; ++blk){
                int r0 = blk*2, r1 = blk*2 + 1;
                ah[blk*4+0] = cvt_tf32(eA[r0]);
                ah[blk*4+1] = cvt_tf32(eA[r1]);
                ah[blk*4+2] = cvt_tf32(eB[r0]);
                ah[blk*4+3] = cvt_tf32(eB[r1]);
                al[blk*4+0] = cvt_tf32(eA[r0] - __uint_as_float(ah[blk*4+0]));
                al[blk*4+1] = cvt_tf32(eA[r1] - __uint_as_float(ah[blk*4+1]));
                al[blk*4+2] = cvt_tf32(eB[r0] - __uint_as_float(ah[blk*4+2]));
                al[blk*4+3] = cvt_tf32(eB[r1] - __uint_as_float(ah[blk*4+3]));
            }

            const float* vA = &sVh[ja*VSTR + g];
            const float* vB = &sVh[jb*VSTR + g];
#pragma unroll
            for (int nb = 0; nb < 8; ++nb){
                unsigned b0 = __float_as_uint(vA[nb*8]);
                unsigned b1 = __float_as_uint(vB[nb*8]);
                // block 0 (rows g, g+8): lo then hi
                asm volatile(
                    "mma.sync.aligned.m16n8k8.row.col.f32.tf32.tf32.f32 "
                    "{%0,%1,%2,%3}, {%4,%5,%6,%7}, {%8,%9}, {%0,%1,%2,%3};"
                    : "+f"(acc0[nb][0]), "+f"(acc0[nb][1]),
                      "+f"(acc0[nb][2]), "+f"(acc0[nb][3])
                    : "r"(al[0]), "r"(al[1]), "r"(al[2]), "r"(al[3]),
                      "r"(b0), "r"(b1));
                asm volatile(
                    "mma.sync.aligned.m16n8k8.row.col.f32.tf32.tf32.f32 "
                    "{%0,%1,%2,%3}, {%4,%5,%6,%7}, {%8,%9}, {%0,%1,%2,%3};"
                    : "+f"(acc0[nb][0]), "+f"(acc0[nb][1]),
                      "+f"(acc0[nb][2]), "+f"(acc0[nb][3])
                    : "r"(ah[0]), "r"(ah[1]), "r"(ah[2]), "r"(ah[3]),
                      "r"(b0), "r"(b1));
                // block 1 (rows g+16, g+24): same B fragments
                asm volatile(
                    "mma.sync.aligned.m16n8k8.row.col.f32.tf32.tf32.f32 "
                    "{%0,%1,%2,%3}, {%4,%5,%6,%7}, {%8,%9}, {%0,%1,%2,%3};"
                    : "+f"(acc1[nb][0]), "+f"(acc1[nb][1]),
                      "+f"(acc1[nb][2]), "+f"(acc1[nb][3])
                    : "r"(al[4]), "r"(al[5]), "r"(al[6]), "r"(al[7]),
                      "r"(b0), "r"(b1));
                asm volatile(
                    "mma.sync.aligned.m16n8k8.row.col.f32.tf32.tf32.f32 "
                    "{%0,%1,%2,%3}, {%4,%5,%6,%7}, {%8,%9}, {%0,%1,%2,%3};"
                    : "+f"(acc1[nb][0]), "+f"(acc1[nb][1]),
                      "+f"(acc1[nb][2]), "+f"(acc1[nb][3])
                    : "r"(ah[4]), "r"(ah[5]), "r"(ah[6]), "r"(ah[7]),
                      "r"(b0), "r"(b1));
            }
        }
        __syncthreads();
    }

    // row sums: reduce over the 4 tig lanes (xor 1, 2)
#pragma unroll
    for (int r = 0; r < 4; ++r){
        ps[r] += __shfl_xor_sync(0xffffffffu, ps[r], 1);
        ps[r] += __shfl_xor_sync(0xffffffffu, ps[r], 2);
    }
    const float inv0 = 1.0f/ps[0], inv1 = 1.0f/ps[1];
    const float inv2 = 1.0f/ps[2], inv3 = 1.0f/ps[3];

#pragma unroll
    for (int nb = 0; nb < 8; ++nb){
        size_t col = h*DK + nb*8 + 2*tig;
        size_t o0 = ((size_t)(b*SEQ + ibase +  0))*EMB + col;
        size_t o1 = ((size_t)(b*SEQ + ibase +  8))*EMB + col;
        size_t o2 = ((size_t)(b*SEQ + ibase + 16))*EMB + col;
        size_t o3 = ((size_t)(b*SEQ + ibase + 24))*EMB + col;
        *(float2*)&out[o0] = make_float2(acc0[nb][0]*inv0, acc0[nb][1]*inv0);
        *(float2*)&out[o1] = make_float2(acc0[nb][2]*inv1, acc0[nb][3]*inv1);
        *(float2*)&out[o2] = make_float2(acc1[nb][0]*inv2, acc1[nb][1]*inv2);
        *(float2*)&out[o3] = make_float2(acc1[nb][2]*inv3, acc1[nb][3]*inv3);
    }
}

extern "C" void kernel_launch(void* const* d_in, const int* in_sizes, int n_in,
                              void* d_out, int out_size){
    const float* x = (const float*)d_in[0];
    float* out = (float*)d_out;
    precompute_cs<<<(BH*NW*SEQ)/256, 256>>>(x);
    precompute_vh<<<((size_t)BH*SEQ*16)/256, 256>>>(x);
    dim3 grid(SEQ/TM, BH);
    qk_attn4<<<grid, 128>>>(out);
}